// round 4
// baseline (speedup 1.0000x reference)
#include <cuda_runtime.h>

#define B 8
#define T_IN 512
#define D 384
#define VPR (D / 4)          // 96 float4s per row
#define T_MEL 3584
#define MEL_MAX 2048

// frame -> token map (-1 = zero row)
__device__ int g_idx[B * MEL_MAX];

// ---------------- prep: scan + pitch avg + dec_lens + g_idx ----------------
__global__ void __launch_bounds__(512) prep_kernel(const int* __restrict__ dur,
                                                   const float* __restrict__ pitch,
                                                   float* __restrict__ dec_lens_out,
                                                   float* __restrict__ pitch_avg_out) {
    const int b = blockIdx.x;
    const int tid = threadIdx.x;

    __shared__ int cum[T_IN + 1];
    __shared__ int wsum[4];

    // shuffle-based scan: threads 0..127, int4 each
    if (tid < 128) {
        int4 dv = ((const int4*)(dur + b * T_IN))[tid];
        int s0 = dv.x, s1 = s0 + dv.y, s2 = s1 + dv.z, s3 = s2 + dv.w;
        int v = s3;
        const int lane = tid & 31;
        #pragma unroll
        for (int off = 1; off < 32; off <<= 1) {
            int n = __shfl_up_sync(0xffffffffu, v, off);
            if (lane >= off) v += n;
        }
        if (lane == 31) wsum[tid >> 5] = v;
        cum[4 * tid + 1] = v - s3 + s0;   // store partial; fix warp offset after barrier
        cum[4 * tid + 2] = v - s3 + s1;
        cum[4 * tid + 3] = v - s3 + s2;
        cum[4 * tid + 4] = v;
        if (tid == 0) cum[0] = 0;
    }
    __syncthreads();
    if (tid < 128) {
        const int wid = tid >> 5;
        int woff = 0;
        #pragma unroll
        for (int w = 0; w < 3; w++) if (w < wid) woff += wsum[w];
        if (woff) {
            cum[4 * tid + 1] += woff;
            cum[4 * tid + 2] += woff;
            cum[4 * tid + 3] += woff;
            cum[4 * tid + 4] += woff;
        }
    }
    // init idx to -1 while scan finalizes (no dependence on cum)
    int* idx = g_idx + b * MEL_MAX;
    #pragma unroll
    for (int k = 0; k < 4; k++) idx[tid + 512 * k] = -1;
    __syncthreads();

    const int start = cum[tid];
    const int end = cum[tid + 1];
    const int total = cum[T_IN];

    if (tid == 0)
        dec_lens_out[b] = (float)(total < MEL_MAX ? total : MEL_MAX);

    // pitch average (N_FORMANTS = 1)
    {
        const float* p = pitch + (size_t)b * T_MEL;
        float s = 0.0f, cnt = 0.0f;
        for (int m = start; m < end; m++) {
            float pv = __ldg(&p[m]);
            s += pv;
            if (pv != 0.0f) cnt += 1.0f;
        }
        pitch_avg_out[b * T_IN + tid] = (cnt != 0.0f) ? (s / cnt) : 0.0f;
    }

    // frame -> token (overwrites -1); needs init done for all threads
    __syncthreads();
    const int e = end < MEL_MAX ? end : MEL_MAX;
    for (int m = start; m < e; m++) idx[m] = tid;
}

// ---------------- gather: 4 independent rows per thread ----------------
// block = 384 threads = 4 row-groups x 96 lanes; block covers 16 rows.
__global__ void __launch_bounds__(384) gather_kernel(const float* __restrict__ enc,
                                                     float* __restrict__ out) {
    const int lane = threadIdx.x % VPR;
    const int rsub = threadIdx.x / VPR;          // 0..3
    const int row0 = blockIdx.x * 16 + rsub;     // rows row0 + 4k
    const int b = (blockIdx.x * 16) >> 11;       // 128 blocks per batch

    // phase 1: 4 independent idx loads
    int t[4];
    #pragma unroll
    for (int k = 0; k < 4; k++) t[k] = __ldg(&g_idx[row0 + 4 * k]);

    // phase 2: 4 independent gathers
    const float4* encb = (const float4*)enc + (size_t)b * T_IN * VPR + lane;
    float4 v[4];
    #pragma unroll
    for (int k = 0; k < 4; k++) {
        v[k] = (t[k] >= 0) ? __ldg(encb + (size_t)t[k] * VPR)
                           : make_float4(0.f, 0.f, 0.f, 0.f);
    }

    // phase 3: 4 coalesced stores
    float4* outp = (float4*)out + (size_t)row0 * VPR + lane;
    #pragma unroll
    for (int k = 0; k < 4; k++) outp[(size_t)(4 * k) * VPR] = v[k];
}

extern "C" void kernel_launch(void* const* d_in, const int* in_sizes, int n_in,
                              void* d_out, int out_size) {
    const float* enc_out = (const float*)d_in[0];   // [B, T_IN, D]
    const int* durations = (const int*)d_in[1];     // [B, T_IN]
    const float* pitch = (const float*)d_in[2];     // [B, 1, T_MEL]

    float* out = (float*)d_out;
    float* enc_rep = out;                               // B*MEL_MAX*D
    float* dec_lens = out + (size_t)B * MEL_MAX * D;    // B
    float* pitch_avg = dec_lens + B;                    // B*T_IN

    prep_kernel<<<B, 512>>>(durations, pitch, dec_lens, pitch_avg);
    gather_kernel<<<B * MEL_MAX / 16, 384>>>(enc_out, enc_rep);
}

// round 5
// speedup vs baseline: 1.1275x; 1.1275x over previous
#include <cuda_runtime.h>

#define B 8
#define T_IN 512
#define D 384
#define VPR (D / 4)          // 96 float4s per row
#define T_MEL 3584
#define MEL_MAX 2048
#define MAXREP 8

// cumulative durations: g_cum[b*(T_IN+1) + k] = sum of dur[b][0..k)
__device__ int g_cum[B * (T_IN + 1)];

// ---------------- kernel 1: tiny scan per batch ----------------
__global__ void __launch_bounds__(128) scan_kernel(const int* __restrict__ dur,
                                                   float* __restrict__ dec_lens_out) {
    const int b = blockIdx.x;
    const int tid = threadIdx.x;
    __shared__ int wsum[4];

    int4 dv = ((const int4*)(dur + b * T_IN))[tid];
    int s0 = dv.x, s1 = s0 + dv.y, s2 = s1 + dv.z, s3 = s2 + dv.w;
    int v = s3;
    const int lane = tid & 31;
    #pragma unroll
    for (int off = 1; off < 32; off <<= 1) {
        int n = __shfl_up_sync(0xffffffffu, v, off);
        if (lane >= off) v += n;
    }
    if (lane == 31) wsum[tid >> 5] = v;
    __syncthreads();
    const int wid = tid >> 5;
    int woff = 0;
    #pragma unroll
    for (int w = 0; w < 3; w++) if (w < wid) woff += wsum[w];
    const int base = woff + v - s3;          // exclusive prefix of this int4

    int* cum = g_cum + b * (T_IN + 1);
    cum[4 * tid + 1] = base + s0;
    cum[4 * tid + 2] = base + s1;
    cum[4 * tid + 3] = base + s2;
    cum[4 * tid + 4] = base + s3;
    if (tid == 0) cum[0] = 0;
    if (tid == 127) {
        int total = base + s3;
        dec_lens_out[b] = (float)(total < MEL_MAX ? total : MEL_MAX);
    }
}

// ---------------- kernel 2: producer-side scatter + pitch + zero-fill ----------------
// blocks [0, 1024): token scatter, 4 tokens per block (4 x 96 lanes)
// blocks [1024, 2048): zero-fill, 16 rows per block (4 x 96 lanes x 4 iters)
__global__ void __launch_bounds__(384) scatter_kernel(const float* __restrict__ enc,
                                                      const float* __restrict__ pitch,
                                                      float* __restrict__ enc_rep,
                                                      float* __restrict__ pitch_avg_out) {
    const int tid = threadIdx.x;
    const int lane = tid % VPR;
    const int rsub = tid / VPR;              // 0..3

    if (blockIdx.x < 1024) {
        // ---- token scatter ----
        const int blk = blockIdx.x;
        const int b = blk >> 7;                        // 128 blocks per batch
        const int tloc = (blk & 127) * 4 + rsub;       // token within batch
        const int* cum = g_cum + b * (T_IN + 1);

        // independent chains: cum loads and row load issue in parallel
        const int start = __ldg(&cum[tloc]);
        const int end = __ldg(&cum[tloc + 1]);
        const float4 val = __ldg((const float4*)enc + ((size_t)b * T_IN + tloc) * VPR + lane);

        const int e = end < MEL_MAX ? end : MEL_MAX;
        float4* outb = (float4*)enc_rep + (size_t)b * MEL_MAX * VPR + lane;
        #pragma unroll
        for (int m = start; m < e; m++)
            outb[(size_t)m * VPR] = val;               // up to 7 independent STG.128

        // pitch average for this token (lane 0 of each row-group)
        if (lane == 0) {
            const float* p = pitch + (size_t)b * T_MEL;
            float s = 0.0f, cnt = 0.0f;
            for (int m = start; m < end; m++) {
                float pv = __ldg(&p[m]);
                s += pv;
                if (pv != 0.0f) cnt += 1.0f;
            }
            pitch_avg_out[b * T_IN + tloc] = (cnt != 0.0f) ? (s / cnt) : 0.0f;
        }
    } else {
        // ---- zero-fill rows [total, MEL_MAX) ----
        const int zb = blockIdx.x - 1024;
        const int b = zb >> 7;                         // 128 blocks per batch
        const int rowbase = (zb & 127) * 16;
        int total = __ldg(&g_cum[b * (T_IN + 1) + T_IN]);
        if (total > MEL_MAX) total = MEL_MAX;
        if (rowbase + 16 <= total) return;             // fully covered by tokens

        const float4 z = make_float4(0.f, 0.f, 0.f, 0.f);
        float4* outb = (float4*)enc_rep + (size_t)b * MEL_MAX * VPR + lane;
        #pragma unroll
        for (int i = 0; i < 4; i++) {
            const int m = rowbase + rsub + 4 * i;
            if (m >= total)
                outb[(size_t)m * VPR] = z;
        }
    }
}

extern "C" void kernel_launch(void* const* d_in, const int* in_sizes, int n_in,
                              void* d_out, int out_size) {
    const float* enc_out = (const float*)d_in[0];   // [B, T_IN, D]
    const int* durations = (const int*)d_in[1];     // [B, T_IN]
    const float* pitch = (const float*)d_in[2];     // [B, 1, T_MEL]

    float* out = (float*)d_out;
    float* enc_rep = out;                               // B*MEL_MAX*D
    float* dec_lens = out + (size_t)B * MEL_MAX * D;    // B
    float* pitch_avg = dec_lens + B;                    // B*T_IN

    scan_kernel<<<B, 128>>>(durations, dec_lens);
    scatter_kernel<<<2048, 384>>>(enc_out, pitch, enc_rep, pitch_avg);
}